// round 13
// baseline (speedup 1.0000x reference)
#include <cuda_runtime.h>
#include <cuda_fp16.h>
#include <cstdint>

// ---------------- problem dims ----------------
#define T_DIM 256
#define HW    128
#define HW2   (HW*HW)
#define KW    129      // half-spectrum bins along W (Hermitian)
#define KWS   132      // padded row stride
#define BD    2

// ---------------- device scratch ----------------
__device__ static float2  d_bufA[(size_t)BD*T_DIM*HW*KWS];
__device__ static __half2 d_bufB[(size_t)BD*T_DIM*T_DIM*KWS];   // fp16 forward spectrum (re,im)
__device__ static __half2 d_bufC[(size_t)BD*T_DIM*T_DIM*KWS];   // fp16 filtered spectrum (scaled by 1/512)
__device__ static float2  d_W512[256];                      // exp(-2*pi*i*k/512), k<256
__device__ static float2  d_W256[256];                      // exp(-2*pi*i*k/256)
__device__ static int     d_cols[2][256][256];
__device__ static float   d_vals[2][256][256];
__device__ static int     d_cnt [2][256];

// ---------------- complex helpers ----------------
static __device__ __forceinline__ float2 cadd(float2 a, float2 b){ return make_float2(a.x+b.x, a.y+b.y); }
static __device__ __forceinline__ float2 csub(float2 a, float2 b){ return make_float2(a.x-b.x, a.y-b.y); }
static __device__ __forceinline__ float2 cmul(float2 a, float2 b){ return make_float2(a.x*b.x - a.y*b.y, a.x*b.y + a.y*b.x); }
static __device__ __forceinline__ float2 cmulc(float2 a, float2 b){ return make_float2(a.x*b.x + a.y*b.y, a.y*b.x - a.x*b.y); } // a*conj(b)
static __device__ __forceinline__ float2 rot_mi(float2 a){ return make_float2(a.y, -a.x); }
static __device__ __forceinline__ float2 rot_pi(float2 a){ return make_float2(-a.y, a.x); }

static __device__ __forceinline__ __half2 c2h(float2 a){ return __floats2half2_rn(a.x, a.y); }
static __device__ __forceinline__ float2  h2c(__half2 a){ return __half22float2(a); }

static __device__ __forceinline__ constexpr int br4(int s){
    return ((s&1)<<3) | ((s&2)<<1) | ((s&4)>>1) | ((s&8)>>3);
}

// W16^n = exp(-2*pi*i*n/16), n=0..7 (hardcoded)
static __device__ __forceinline__ float2 w16f(int n, int sgn){
    const float c[8]={1.f,0.92387953251f,0.70710678119f,0.38268343236f,0.f,-0.38268343236f,-0.70710678119f,-0.92387953251f};
    const float s[8]={0.f,0.38268343236f,0.70710678119f,0.92387953251f,1.f,0.92387953251f,0.70710678119f,0.38268343236f};
    return make_float2(c[n], sgn > 0 ? -s[n] : s[n]);
}

// In-register DFT16, DIF: natural-order input, slot s holds X[br4(s)].
template<int SGN>
static __device__ __forceinline__ void dft16(float2 r[16])
{
    #pragma unroll
    for (int n = 0; n < 8; n++) {
        float2 a = r[n], b = r[n+8];
        r[n]   = cadd(a,b);
        r[n+8] = cmul(csub(a,b), w16f(n, SGN));
    }
    #pragma unroll
    for (int blk = 0; blk < 16; blk += 8)
        #pragma unroll
        for (int n = 0; n < 4; n++) {
            float2 a = r[blk+n], b = r[blk+n+4];
            r[blk+n]   = cadd(a,b);
            r[blk+n+4] = cmul(csub(a,b), w16f(2*n, SGN));
        }
    #pragma unroll
    for (int blk = 0; blk < 16; blk += 4) {
        { float2 a = r[blk],   b = r[blk+2]; r[blk]   = cadd(a,b); r[blk+2] = csub(a,b); }
        { float2 a = r[blk+1], b = r[blk+3]; r[blk+1] = cadd(a,b);
          float2 d = csub(a,b); r[blk+3] = (SGN > 0) ? rot_mi(d) : rot_pi(d); }
    }
    #pragma unroll
    for (int blk = 0; blk < 16; blk += 2) {
        float2 a = r[blk], b = r[blk+1];
        r[blk] = cadd(a,b); r[blk+1] = csub(a,b);
    }
}

// ---------------- init: twiddles + CSR of mtx/mtxi (warp-per-row ballot compaction) ----------------
// d_vals[1] absorbs the H- and W-axis inverse-FFT normalization 1/(256*256).
__global__ __launch_bounds__(256) void k_init(const float* __restrict__ mtx, const float* __restrict__ mtxi,
                                              const float* __restrict__ gridz)
{
    if (blockIdx.x == 0) {
        int t = threadIdx.x;
        float s, c;
        sincospif((float)t / 256.0f, &s, &c);
        d_W512[t] = make_float2(c, -s);
        sincospif((float)t / 128.0f, &s, &c);
        d_W256[t] = make_float2(c, -s);
    }
    int w    = (blockIdx.x * 256 + threadIdx.x) >> 5;   // warp id in [0,512)
    int lane = threadIdx.x & 31;
    int mat  = w >> 8;
    int m    = w & 255;
    const float* M = mat ? mtxi : mtx;
    const float INVNORM_HW = 1.0f / 65536.0f;           // 1/(256*256)
    int cnt = 0;
    #pragma unroll
    for (int base = 0; base < 256; base += 32) {
        int k = base + lane;
        float v = M[m*256 + k];
        bool act = (v != 0.0f);
        unsigned mask = __ballot_sync(0xffffffffu, act);
        if (act) {
            int pos = cnt + __popc(mask & ((1u << lane) - 1u));
            float g;
            if (mat == 0) { float z = gridz[k]; float z2 = z*z; g = z2*z2; }
            else           g = INVNORM_HW;
            d_cols[mat][m][pos] = k;
            d_vals[mat][m][pos] = v * g;
        }
        cnt += __popc(mask);
    }
    if (lane == 0) d_cnt[mat][m] = cnt;
}

// ============ Pass A: fused resample + W-axis forward (128 real -> 256-pt, keep 129) ============
__global__ __launch_bounds__(256) void k_fft_w_fwd(const float* __restrict__ feature)
{
    __shared__ float2 Xs[16][16][17];   // [line][k2][n1 + pad]
    __shared__ float2 Wtw[256];
    int tid = threadIdx.x;
    Wtw[tid] = d_W256[tid];
    int n1 = tid & 15, ln = tid >> 4;
    int G  = blockIdx.x*16 + ln;        // (bd*256 + m)*128 + h
    int h  = G & 127;
    int m  = (G >> 7) & 255;
    int bd = G >> 15;
    int nnz = d_cnt[0][m];
    float acc[8];
    #pragma unroll
    for (int i = 0; i < 8; i++) acc[i] = 0.f;
    for (int j = 0; j < nnz; j++) {
        float v = d_vals[0][m][j];
        const float* fp = feature + (((size_t)(bd*T_DIM + d_cols[0][m][j]))*HW + h)*HW;
        #pragma unroll
        for (int n2 = 0; n2 < 8; n2++) acc[n2] += v * fp[n1 + 16*n2];
    }
    float2 r[16];
    #pragma unroll
    for (int n2 = 0; n2 < 8; n2++)  r[n2] = make_float2(acc[n2], 0.f);
    #pragma unroll
    for (int n2 = 8; n2 < 16; n2++) r[n2] = make_float2(0.f, 0.f);
    __syncthreads();
    dft16<1>(r);
    #pragma unroll
    for (int s = 0; s < 16; s++) {
        const int k2 = br4(s);
        Xs[ln][k2][n1] = cmul(r[s], Wtw[n1*k2]);
    }
    __syncthreads();
    int k2p = n1;
    #pragma unroll
    for (int j = 0; j < 16; j++) r[j] = Xs[ln][k2p][j];
    dft16<1>(r);
    float2* out = d_bufA + (size_t)G*KWS;
    #pragma unroll
    for (int s = 0; s < 16; s++) {
        const int k1 = br4(s);
        int k = k2p + 16*k1;
        if (k <= 128) out[k] = r[s];
    }
}

// ============ Pass B: H-axis forward (128 -> 256, four-step 16x16 register FFT) ============
__global__ __launch_bounds__(256) void k_fft_h_fwd()
{
    __shared__ float2 Xs[16][17][17];   // [k2][n1][kwl]
    __shared__ float2 Wtw[256];
    int tid = threadIdx.x;
    Wtw[tid] = d_W256[tid];
    int kwl = tid & 15, n1 = tid >> 4;
    int kw = blockIdx.x*16 + kwl;
    bool ok = kw < KW;
    const float2* in = d_bufA + ((size_t)(blockIdx.z*T_DIM + blockIdx.y))*HW*KWS;
    float2 r[16];
    #pragma unroll
    for (int n2 = 0; n2 < 8; n2++)
        r[n2] = ok ? in[(n1 + 16*n2)*KWS + kw] : make_float2(0.f,0.f);
    #pragma unroll
    for (int n2 = 8; n2 < 16; n2++) r[n2] = make_float2(0.f,0.f);
    __syncthreads();
    dft16<1>(r);
    #pragma unroll
    for (int s = 0; s < 16; s++) {
        const int k2 = br4(s);
        Xs[k2][n1][kwl] = cmul(r[s], Wtw[n1*k2]);
    }
    __syncthreads();
    int k2p = n1;
    #pragma unroll
    for (int j = 0; j < 16; j++) r[j] = Xs[k2p][j][kwl];
    dft16<1>(r);
    __half2* out = d_bufB + ((size_t)(blockIdx.z*T_DIM + blockIdx.y))*T_DIM*KWS;
    if (ok) {
        #pragma unroll
        for (int s = 0; s < 16; s++) {
            int kh = k2p + 16*br4(s);
            out[kh*KWS + kw] = c2h(r[s]);
        }
    }
}

// ============ Pass C: T-axis even/odd split — fp16 bufB in, fp16 bufC out (×1/512) ============
__global__ __launch_bounds__(256, 2) void k_fft_t(const float* __restrict__ pr, const float* __restrict__ pi)
{
    __shared__ float2 Xs[16][16][17];   // [a][b][col]
    __shared__ float2 Wtw[256];         // W256
    __shared__ float2 W5[256];          // W512^t
    int tid = threadIdx.x;
    Wtw[tid] = d_W256[tid];
    W5[tid]  = d_W512[tid];
    int col = tid & 15, tt = tid >> 4;
    int bd = col >> 3, kwl = col & 7;
    int kw = blockIdx.x*8 + kwl;
    int kh = blockIdx.y;
    bool ok = kw < KW;
    const int TSTR = T_DIM*KWS;
    const size_t BDSTR = (size_t)T_DIM*T_DIM*KWS;
    const __half2* base = d_bufB + (size_t)bd*BDSTR + (size_t)kh*KWS;
    __half2*      obase = d_bufC + (size_t)bd*BDSTR + (size_t)kh*KWS;
    const float TSCALE = 1.0f / 512.0f;     // T-axis inverse norm (rest folded into mtxi CSR)
    __syncthreads();                    // twiddle tables ready

    float2 r[16], rin[16], Se[16];

    // ================= EVEN chain: S_e = IFFT256( FFT256(x) * psf[2k] ) =================
    #pragma unroll
    for (int n2 = 0; n2 < 16; n2++)
        r[n2] = ok ? h2c(base[(size_t)(tt + 16*n2)*TSTR + kw]) : make_float2(0.f,0.f);
    dft16<1>(r);                        // over n2 -> k2 in bitrev slots
    #pragma unroll
    for (int s = 0; s < 16; s++) { const int k2 = br4(s); Xs[k2][tt][col] = cmul(r[s], Wtw[tt*k2]); }
    __syncthreads();
    #pragma unroll
    for (int j = 0; j < 16; j++) r[j] = Xs[tt][j][col];    // thread owns k2p = tt
    dft16<1>(r);                        // slot s: X256[tt + 16*br4(s)]
    #pragma unroll
    for (int s = 0; s < 16; s++) {      // psf multiply + reg permute into inverse input order
        const int k1 = br4(s);
        int k = tt + 16*k1;
        float2 p = make_float2(0.f,0.f);
        if (ok) { size_t o = ((size_t)(2*k)*256 + kh)*256 + kw; p = make_float2(pr[o], pi[o]); }
        rin[k1] = cmul(r[s], p);
    }
    __syncthreads();                    // Xs reads done, safe to overwrite
    dft16<-1>(rin);                     // over k1 -> n1 in bitrev slots
    #pragma unroll
    for (int s = 0; s < 16; s++) { const int n1 = br4(s); Xs[n1][tt][col] = cmulc(rin[s], Wtw[n1*tt]); }
    __syncthreads();
    #pragma unroll
    for (int j = 0; j < 16; j++) Se[j] = Xs[tt][j][col];   // thread owns n1p = tt
    dft16<-1>(Se);                      // slot s: S_e[tt + 16*br4(s)]
    __syncthreads();                    // before odd chain reuses Xs

    // ================= ODD chain: S_o = IFFT256( FFT256(x*W512^t) * psf[2k+1] ) =================
    #pragma unroll
    for (int n2 = 0; n2 < 16; n2++) {
        int t = tt + 16*n2;
        float2 v = ok ? h2c(base[(size_t)t*TSTR + kw]) : make_float2(0.f,0.f);
        r[n2] = cmul(v, W5[t]);
    }
    dft16<1>(r);
    #pragma unroll
    for (int s = 0; s < 16; s++) { const int k2 = br4(s); Xs[k2][tt][col] = cmul(r[s], Wtw[tt*k2]); }
    __syncthreads();
    #pragma unroll
    for (int j = 0; j < 16; j++) r[j] = Xs[tt][j][col];
    dft16<1>(r);
    #pragma unroll
    for (int s = 0; s < 16; s++) {
        const int k1 = br4(s);
        int k = tt + 16*k1;
        float2 p = make_float2(0.f,0.f);
        if (ok) { size_t o = ((size_t)(2*k+1)*256 + kh)*256 + kw; p = make_float2(pr[o], pi[o]); }
        rin[k1] = cmul(r[s], p);
    }
    __syncthreads();
    dft16<-1>(rin);
    #pragma unroll
    for (int s = 0; s < 16; s++) { const int n1 = br4(s); Xs[n1][tt][col] = cmulc(rin[s], Wtw[n1*tt]); }
    __syncthreads();
    #pragma unroll
    for (int j = 0; j < 16; j++) r[j] = Xs[tt][j][col];
    dft16<-1>(r);                       // slot s: S_o[tt + 16*br4(s)]

    // ================= combine + store fp16, scaled by 1/512 (crop t < 256) =================
    if (ok) {
        #pragma unroll
        for (int s = 0; s < 16; s++) {
            int n = tt + 16*br4(s);
            float2 y = cadd(Se[s], cmulc(r[s], W5[n]));   // + conj(W512^n) * S_o
            obase[(size_t)n*TSTR + kw] = c2h(make_float2(y.x*TSCALE, y.y*TSCALE));
        }
    }
}

// ============ Pass D: H-axis inverse (256 -> crop 128, four-step) — fp16 bufC in ============
__global__ __launch_bounds__(256) void k_fft_h_inv()
{
    __shared__ float2 Xs[16][17][17];   // [n1][k2][kwl]
    __shared__ float2 Wtw[256];
    int tid = threadIdx.x;
    Wtw[tid] = d_W256[tid];
    int kwl = tid & 15, k2 = tid >> 4;
    int kw = blockIdx.x*16 + kwl;
    bool ok = kw < KW;
    const __half2* in = d_bufC + ((size_t)(blockIdx.z*T_DIM + blockIdx.y))*T_DIM*KWS;
    float2 r[16];
    #pragma unroll
    for (int k1 = 0; k1 < 16; k1++)
        r[k1] = ok ? h2c(in[(k2 + 16*k1)*KWS + kw]) : make_float2(0.f,0.f);
    __syncthreads();
    dft16<-1>(r);
    #pragma unroll
    for (int s = 0; s < 16; s++) {
        const int n1 = br4(s);
        Xs[n1][k2][kwl] = cmulc(r[s], Wtw[n1*k2]);
    }
    __syncthreads();
    int n1p = k2;
    #pragma unroll
    for (int j = 0; j < 16; j++) r[j] = Xs[n1p][j][kwl];
    dft16<-1>(r);
    float2* out = d_bufA + ((size_t)(blockIdx.z*T_DIM + blockIdx.y))*HW*KWS;
    if (ok) {
        #pragma unroll
        for (int s = 0; s < 16; s++) {
            const int n2 = br4(s);
            if (n2 < 8) out[(n1p + 16*n2)*KWS + kw] = r[s];
        }
    }
}

// ============ Pass E: fused inverse-resample + W-axis inverse C2R ============
// (mtxi CSR weights carry the 1/(256*256) normalization)
__global__ __launch_bounds__(256) void k_fft_w_inv(float* __restrict__ outp)
{
    __shared__ float2 Xs[16][16][17];   // [line][n1][k2 + pad]
    __shared__ float2 Wtw[256];
    int tid = threadIdx.x;
    Wtw[tid] = d_W256[tid];
    int tt = tid & 15, ln = tid >> 4;
    int G  = blockIdx.x*16 + ln;        // (bd*256 + m)*128 + h
    int h  = G & 127;
    int m  = (G >> 7) & 255;
    int bd = G >> 15;
    int nnz = d_cnt[1][m];
    float2 r[16];
    #pragma unroll
    for (int i = 0; i < 16; i++) r[i] = make_float2(0.f, 0.f);
    for (int j = 0; j < nnz; j++) {
        float v = d_vals[1][m][j];
        const float2* in = d_bufA + ((size_t)(bd*T_DIM + d_cols[1][m][j])*HW + h)*KWS;
        #pragma unroll
        for (int k1 = 0; k1 < 16; k1++) {
            int k = tt + 16*k1;
            float2 c;
            if (k <= 128) c = in[k];
            else { float2 q = in[256-k]; c = make_float2(q.x, -q.y); }
            r[k1].x += v * c.x; r[k1].y += v * c.y;
        }
    }
    __syncthreads();
    dft16<-1>(r);
    #pragma unroll
    for (int s = 0; s < 16; s++) {
        const int n1 = br4(s);
        Xs[ln][n1][tt] = cmulc(r[s], Wtw[n1*tt]);
    }
    __syncthreads();
    int n1p = tt;
    #pragma unroll
    for (int j = 0; j < 16; j++) r[j] = Xs[ln][n1p][j];
    dft16<-1>(r);
    float* op = outp + (size_t)G*HW;
    #pragma unroll
    for (int s = 0; s < 16; s++) {
        const int n2 = br4(s);
        if (n2 < 8) op[n1p + 16*n2] = r[s].x;
    }
}

// ---------------- launch ----------------
extern "C" void kernel_launch(void* const* d_in, const int* in_sizes, int n_in,
                              void* d_out, int out_size)
{
    (void)in_sizes; (void)n_in; (void)out_size;
    const float* feature = (const float*)d_in[0];
    const float* gridz   = (const float*)d_in[1];
    const float* mtx     = (const float*)d_in[2];
    const float* mtxi    = (const float*)d_in[3];
    const float* pr      = (const float*)d_in[4];
    const float* pi      = (const float*)d_in[5];
    float* out = (float*)d_out;

    k_init<<<64, 256>>>(mtx, mtxi, gridz);                   // parallel CSR + twiddles

    k_fft_w_fwd<<<(BD*T_DIM*HW)/16, 256>>>(feature);         // fused resample + W FFT

    k_fft_h_fwd<<<dim3((KW + 15)/16, T_DIM, BD), 256>>>();   // -> fp16 bufB

    k_fft_t<<<dim3((KW + 7)/8, T_DIM), 256>>>(pr, pi);       // fp16 in, fp16 out (bufC)

    k_fft_h_inv<<<dim3((KW + 15)/16, T_DIM, BD), 256>>>();   // <- fp16 bufC

    k_fft_w_inv<<<(BD*T_DIM*HW)/16, 256>>>(out);             // fused W-inverse + resample
}

// round 16
// speedup vs baseline: 1.4567x; 1.4567x over previous
#include <cuda_runtime.h>
#include <cuda_fp16.h>
#include <cstdint>

// ---------------- problem dims ----------------
#define T_DIM 256
#define HW    128
#define HW2   (HW*HW)
#define KW    129      // half-spectrum bins along W (Hermitian)
#define KWS   132      // padded row stride
#define BD    2

// ---------------- device scratch ----------------
__device__ static __half2 d_bufA[(size_t)BD*T_DIM*HW*KWS];      // fp16 W-spectrum / H-inv output
__device__ static __half2 d_bufB[(size_t)BD*T_DIM*T_DIM*KWS];   // fp16 forward spectrum (re,im)
__device__ static float2  d_bufC[(size_t)BD*T_DIM*T_DIM*KWS];   // fp32 filtered spectrum (x 1/512)
__device__ static float2  d_W512[256];                      // exp(-2*pi*i*k/512), k<256
__device__ static float2  d_W256[256];                      // exp(-2*pi*i*k/256)
__device__ static int     d_cols[2][256][256];
__device__ static float   d_vals[2][256][256];
__device__ static int     d_cnt [2][256];

// ---------------- complex helpers ----------------
static __device__ __forceinline__ float2 cadd(float2 a, float2 b){ return make_float2(a.x+b.x, a.y+b.y); }
static __device__ __forceinline__ float2 csub(float2 a, float2 b){ return make_float2(a.x-b.x, a.y-b.y); }
static __device__ __forceinline__ float2 cmul(float2 a, float2 b){ return make_float2(a.x*b.x - a.y*b.y, a.x*b.y + a.y*b.x); }
static __device__ __forceinline__ float2 cmulc(float2 a, float2 b){ return make_float2(a.x*b.x + a.y*b.y, a.y*b.x - a.x*b.y); } // a*conj(b)
static __device__ __forceinline__ float2 rot_mi(float2 a){ return make_float2(a.y, -a.x); }
static __device__ __forceinline__ float2 rot_pi(float2 a){ return make_float2(-a.y, a.x); }

static __device__ __forceinline__ __half2 c2h(float2 a){ return __floats2half2_rn(a.x, a.y); }
static __device__ __forceinline__ float2  h2c(__half2 a){ return __half22float2(a); }

static __device__ __forceinline__ constexpr int br4(int s){
    return ((s&1)<<3) | ((s&2)<<1) | ((s&4)>>1) | ((s&8)>>3);
}

// W16^n = exp(-2*pi*i*n/16), n=0..7 (hardcoded)
static __device__ __forceinline__ float2 w16f(int n, int sgn){
    const float c[8]={1.f,0.92387953251f,0.70710678119f,0.38268343236f,0.f,-0.38268343236f,-0.70710678119f,-0.92387953251f};
    const float s[8]={0.f,0.38268343236f,0.70710678119f,0.92387953251f,1.f,0.92387953251f,0.70710678119f,0.38268343236f};
    return make_float2(c[n], sgn > 0 ? -s[n] : s[n]);
}

// In-register DFT16, DIF: natural-order input, slot s holds X[br4(s)].
template<int SGN>
static __device__ __forceinline__ void dft16(float2 r[16])
{
    #pragma unroll
    for (int n = 0; n < 8; n++) {
        float2 a = r[n], b = r[n+8];
        r[n]   = cadd(a,b);
        r[n+8] = cmul(csub(a,b), w16f(n, SGN));
    }
    #pragma unroll
    for (int blk = 0; blk < 16; blk += 8)
        #pragma unroll
        for (int n = 0; n < 4; n++) {
            float2 a = r[blk+n], b = r[blk+n+4];
            r[blk+n]   = cadd(a,b);
            r[blk+n+4] = cmul(csub(a,b), w16f(2*n, SGN));
        }
    #pragma unroll
    for (int blk = 0; blk < 16; blk += 4) {
        { float2 a = r[blk],   b = r[blk+2]; r[blk]   = cadd(a,b); r[blk+2] = csub(a,b); }
        { float2 a = r[blk+1], b = r[blk+3]; r[blk+1] = cadd(a,b);
          float2 d = csub(a,b); r[blk+3] = (SGN > 0) ? rot_mi(d) : rot_pi(d); }
    }
    #pragma unroll
    for (int blk = 0; blk < 16; blk += 2) {
        float2 a = r[blk], b = r[blk+1];
        r[blk] = cadd(a,b); r[blk+1] = csub(a,b);
    }
}

// ---------------- init: twiddles + CSR of mtx/mtxi (warp-per-row ballot compaction) ----------------
// d_vals[1] absorbs the H- and W-axis inverse-FFT normalization 1/(256*256).
__global__ __launch_bounds__(256) void k_init(const float* __restrict__ mtx, const float* __restrict__ mtxi,
                                              const float* __restrict__ gridz)
{
    if (blockIdx.x == 0) {
        int t = threadIdx.x;
        float s, c;
        sincospif((float)t / 256.0f, &s, &c);
        d_W512[t] = make_float2(c, -s);
        sincospif((float)t / 128.0f, &s, &c);
        d_W256[t] = make_float2(c, -s);
    }
    int w    = (blockIdx.x * 256 + threadIdx.x) >> 5;   // warp id in [0,512)
    int lane = threadIdx.x & 31;
    int mat  = w >> 8;
    int m    = w & 255;
    const float* M = mat ? mtxi : mtx;
    const float INVNORM_HW = 1.0f / 65536.0f;           // 1/(256*256)
    int cnt = 0;
    #pragma unroll
    for (int base = 0; base < 256; base += 32) {
        int k = base + lane;
        float v = M[m*256 + k];
        bool act = (v != 0.0f);
        unsigned mask = __ballot_sync(0xffffffffu, act);
        if (act) {
            int pos = cnt + __popc(mask & ((1u << lane) - 1u));
            float g;
            if (mat == 0) { float z = gridz[k]; float z2 = z*z; g = z2*z2; }
            else           g = INVNORM_HW;
            d_cols[mat][m][pos] = k;
            d_vals[mat][m][pos] = v * g;
        }
        cnt += __popc(mask);
    }
    if (lane == 0) d_cnt[mat][m] = cnt;
}

// ============ Pass A: fused resample + W-axis forward (128 real -> 256-pt, keep 129) ============
__global__ __launch_bounds__(256) void k_fft_w_fwd(const float* __restrict__ feature)
{
    __shared__ float2 Xs[16][16][17];   // [line][k2][n1 + pad]
    __shared__ float2 Wtw[256];
    int tid = threadIdx.x;
    Wtw[tid] = d_W256[tid];
    int n1 = tid & 15, ln = tid >> 4;
    int G  = blockIdx.x*16 + ln;        // (bd*256 + m)*128 + h
    int h  = G & 127;
    int m  = (G >> 7) & 255;
    int bd = G >> 15;
    int nnz = d_cnt[0][m];
    float acc[8];
    #pragma unroll
    for (int i = 0; i < 8; i++) acc[i] = 0.f;
    for (int j = 0; j < nnz; j++) {
        float v = d_vals[0][m][j];
        const float* fp = feature + (((size_t)(bd*T_DIM + d_cols[0][m][j]))*HW + h)*HW;
        #pragma unroll
        for (int n2 = 0; n2 < 8; n2++) acc[n2] += v * fp[n1 + 16*n2];
    }
    float2 r[16];
    #pragma unroll
    for (int n2 = 0; n2 < 8; n2++)  r[n2] = make_float2(acc[n2], 0.f);
    #pragma unroll
    for (int n2 = 8; n2 < 16; n2++) r[n2] = make_float2(0.f, 0.f);
    __syncthreads();
    dft16<1>(r);
    #pragma unroll
    for (int s = 0; s < 16; s++) {
        const int k2 = br4(s);
        Xs[ln][k2][n1] = cmul(r[s], Wtw[n1*k2]);
    }
    __syncthreads();
    int k2p = n1;
    #pragma unroll
    for (int j = 0; j < 16; j++) r[j] = Xs[ln][k2p][j];
    dft16<1>(r);
    __half2* out = d_bufA + (size_t)G*KWS;
    #pragma unroll
    for (int s = 0; s < 16; s++) {
        const int k1 = br4(s);
        int k = k2p + 16*k1;
        if (k <= 128) out[k] = c2h(r[s]);
    }
}

// ============ Pass B: H-axis forward (128 -> 256, four-step 16x16 register FFT) ============
__global__ __launch_bounds__(256) void k_fft_h_fwd()
{
    __shared__ float2 Xs[16][17][17];   // [k2][n1][kwl]
    __shared__ float2 Wtw[256];
    int tid = threadIdx.x;
    Wtw[tid] = d_W256[tid];
    int kwl = tid & 15, n1 = tid >> 4;
    int kw = blockIdx.x*16 + kwl;
    bool ok = kw < KW;
    const __half2* in = d_bufA + ((size_t)(blockIdx.z*T_DIM + blockIdx.y))*HW*KWS;
    float2 r[16];
    #pragma unroll
    for (int n2 = 0; n2 < 8; n2++)
        r[n2] = ok ? h2c(in[(n1 + 16*n2)*KWS + kw]) : make_float2(0.f,0.f);
    #pragma unroll
    for (int n2 = 8; n2 < 16; n2++) r[n2] = make_float2(0.f,0.f);
    __syncthreads();
    dft16<1>(r);
    #pragma unroll
    for (int s = 0; s < 16; s++) {
        const int k2 = br4(s);
        Xs[k2][n1][kwl] = cmul(r[s], Wtw[n1*k2]);
    }
    __syncthreads();
    int k2p = n1;
    #pragma unroll
    for (int j = 0; j < 16; j++) r[j] = Xs[k2p][j][kwl];
    dft16<1>(r);
    __half2* out = d_bufB + ((size_t)(blockIdx.z*T_DIM + blockIdx.y))*T_DIM*KWS;
    if (ok) {
        #pragma unroll
        for (int s = 0; s < 16; s++) {
            int kh = k2p + 16*br4(s);
            out[kh*KWS + kw] = c2h(r[s]);
        }
    }
}

// ============ Pass C: T-axis even/odd split — fp16 bufB in, fp32 bufC out (psf x 1/512) ============
__global__ __launch_bounds__(256, 2) void k_fft_t(const float* __restrict__ pr, const float* __restrict__ pi)
{
    __shared__ float2 Xs[16][16][17];   // [a][b][col]
    __shared__ float2 Wtw[256];         // W256
    __shared__ float2 W5[256];          // W512^t
    int tid = threadIdx.x;
    Wtw[tid] = d_W256[tid];
    W5[tid]  = d_W512[tid];
    int col = tid & 15, tt = tid >> 4;
    int bd = col >> 3, kwl = col & 7;
    int kw = blockIdx.x*8 + kwl;
    int kh = blockIdx.y;
    bool ok = kw < KW;
    const int TSTR = T_DIM*KWS;
    const size_t BDSTR = (size_t)T_DIM*T_DIM*KWS;
    const __half2* base = d_bufB + (size_t)bd*BDSTR + (size_t)kh*KWS;
    float2*       obase = d_bufC + (size_t)bd*BDSTR + (size_t)kh*KWS;
    const float TSCALE = 1.0f / 512.0f;     // T-axis inverse norm only (rest in mtxi CSR)
    __syncthreads();                    // twiddle tables ready

    float2 r[16], rin[16], Se[16];

    // ================= EVEN chain: S_e = IFFT256( FFT256(x) * psf[2k] ) =================
    #pragma unroll
    for (int n2 = 0; n2 < 16; n2++)
        r[n2] = ok ? h2c(base[(size_t)(tt + 16*n2)*TSTR + kw]) : make_float2(0.f,0.f);
    dft16<1>(r);                        // over n2 -> k2 in bitrev slots
    #pragma unroll
    for (int s = 0; s < 16; s++) { const int k2 = br4(s); Xs[k2][tt][col] = cmul(r[s], Wtw[tt*k2]); }
    __syncthreads();
    #pragma unroll
    for (int j = 0; j < 16; j++) r[j] = Xs[tt][j][col];    // thread owns k2p = tt
    dft16<1>(r);                        // slot s: X256[tt + 16*br4(s)]
    #pragma unroll
    for (int s = 0; s < 16; s++) {      // psf multiply (x 1/512) + reg permute
        const int k1 = br4(s);
        int k = tt + 16*k1;
        float2 p = make_float2(0.f,0.f);
        if (ok) { size_t o = ((size_t)(2*k)*256 + kh)*256 + kw; p = make_float2(pr[o]*TSCALE, pi[o]*TSCALE); }
        rin[k1] = cmul(r[s], p);
    }
    __syncthreads();                    // Xs reads done, safe to overwrite
    dft16<-1>(rin);                     // over k1 -> n1 in bitrev slots
    #pragma unroll
    for (int s = 0; s < 16; s++) { const int n1 = br4(s); Xs[n1][tt][col] = cmulc(rin[s], Wtw[n1*tt]); }
    __syncthreads();
    #pragma unroll
    for (int j = 0; j < 16; j++) Se[j] = Xs[tt][j][col];   // thread owns n1p = tt
    dft16<-1>(Se);                      // slot s: S_e[tt + 16*br4(s)]
    __syncthreads();                    // before odd chain reuses Xs

    // ================= ODD chain: S_o = IFFT256( FFT256(x*W512^t) * psf[2k+1] ) =================
    #pragma unroll
    for (int n2 = 0; n2 < 16; n2++) {
        int t = tt + 16*n2;
        float2 v = ok ? h2c(base[(size_t)t*TSTR + kw]) : make_float2(0.f,0.f);
        r[n2] = cmul(v, W5[t]);
    }
    dft16<1>(r);
    #pragma unroll
    for (int s = 0; s < 16; s++) { const int k2 = br4(s); Xs[k2][tt][col] = cmul(r[s], Wtw[tt*k2]); }
    __syncthreads();
    #pragma unroll
    for (int j = 0; j < 16; j++) r[j] = Xs[tt][j][col];
    dft16<1>(r);
    #pragma unroll
    for (int s = 0; s < 16; s++) {
        const int k1 = br4(s);
        int k = tt + 16*k1;
        float2 p = make_float2(0.f,0.f);
        if (ok) { size_t o = ((size_t)(2*k+1)*256 + kh)*256 + kw; p = make_float2(pr[o]*TSCALE, pi[o]*TSCALE); }
        rin[k1] = cmul(r[s], p);
    }
    __syncthreads();
    dft16<-1>(rin);
    #pragma unroll
    for (int s = 0; s < 16; s++) { const int n1 = br4(s); Xs[n1][tt][col] = cmulc(rin[s], Wtw[n1*tt]); }
    __syncthreads();
    #pragma unroll
    for (int j = 0; j < 16; j++) r[j] = Xs[tt][j][col];
    dft16<-1>(r);                       // slot s: S_o[tt + 16*br4(s)]

    // ================= combine + store fp32 (crop t < 256) =================
    if (ok) {
        #pragma unroll
        for (int s = 0; s < 16; s++) {
            int n = tt + 16*br4(s);
            float2 y = cadd(Se[s], cmulc(r[s], W5[n]));   // + conj(W512^n) * S_o
            obase[(size_t)n*TSTR + kw] = y;
        }
    }
}

// ============ Pass D: H-axis inverse (256 -> crop 128) — fp32 bufC in, fp16 bufA out ============
__global__ __launch_bounds__(256) void k_fft_h_inv()
{
    __shared__ float2 Xs[16][17][17];   // [n1][k2][kwl]
    __shared__ float2 Wtw[256];
    int tid = threadIdx.x;
    Wtw[tid] = d_W256[tid];
    int kwl = tid & 15, k2 = tid >> 4;
    int kw = blockIdx.x*16 + kwl;
    bool ok = kw < KW;
    const float2* in = d_bufC + ((size_t)(blockIdx.z*T_DIM + blockIdx.y))*T_DIM*KWS;
    float2 r[16];
    #pragma unroll
    for (int k1 = 0; k1 < 16; k1++)
        r[k1] = ok ? in[(k2 + 16*k1)*KWS + kw] : make_float2(0.f,0.f);
    __syncthreads();
    dft16<-1>(r);
    #pragma unroll
    for (int s = 0; s < 16; s++) {
        const int n1 = br4(s);
        Xs[n1][k2][kwl] = cmulc(r[s], Wtw[n1*k2]);
    }
    __syncthreads();
    int n1p = k2;
    #pragma unroll
    for (int j = 0; j < 16; j++) r[j] = Xs[n1p][j][kwl];
    dft16<-1>(r);
    __half2* out = d_bufA + ((size_t)(blockIdx.z*T_DIM + blockIdx.y))*HW*KWS;
    if (ok) {
        #pragma unroll
        for (int s = 0; s < 16; s++) {
            const int n2 = br4(s);
            if (n2 < 8) out[(n1p + 16*n2)*KWS + kw] = c2h(r[s]);
        }
    }
}

// ============ Pass E: fused inverse-resample + W-axis inverse C2R (fp16 bufA in) ============
// (mtxi CSR weights carry the 1/(256*256) normalization)
__global__ __launch_bounds__(256) void k_fft_w_inv(float* __restrict__ outp)
{
    __shared__ float2 Xs[16][16][17];   // [line][n1][k2 + pad]
    __shared__ float2 Wtw[256];
    int tid = threadIdx.x;
    Wtw[tid] = d_W256[tid];
    int tt = tid & 15, ln = tid >> 4;
    int G  = blockIdx.x*16 + ln;        // (bd*256 + m)*128 + h
    int h  = G & 127;
    int m  = (G >> 7) & 255;
    int bd = G >> 15;
    int nnz = d_cnt[1][m];
    float2 r[16];
    #pragma unroll
    for (int i = 0; i < 16; i++) r[i] = make_float2(0.f, 0.f);
    for (int j = 0; j < nnz; j++) {
        float v = d_vals[1][m][j];
        const __half2* in = d_bufA + ((size_t)(bd*T_DIM + d_cols[1][m][j])*HW + h)*KWS;
        #pragma unroll
        for (int k1 = 0; k1 < 16; k1++) {
            int k = tt + 16*k1;
            float2 c;
            if (k <= 128) c = h2c(in[k]);
            else { float2 q = h2c(in[256-k]); c = make_float2(q.x, -q.y); }
            r[k1].x += v * c.x; r[k1].y += v * c.y;
        }
    }
    __syncthreads();
    dft16<-1>(r);
    #pragma unroll
    for (int s = 0; s < 16; s++) {
        const int n1 = br4(s);
        Xs[ln][n1][tt] = cmulc(r[s], Wtw[n1*tt]);
    }
    __syncthreads();
    int n1p = tt;
    #pragma unroll
    for (int j = 0; j < 16; j++) r[j] = Xs[ln][n1p][j];
    dft16<-1>(r);
    float* op = outp + (size_t)G*HW;
    #pragma unroll
    for (int s = 0; s < 16; s++) {
        const int n2 = br4(s);
        if (n2 < 8) op[n1p + 16*n2] = r[s].x;
    }
}

// ---------------- launch ----------------
extern "C" void kernel_launch(void* const* d_in, const int* in_sizes, int n_in,
                              void* d_out, int out_size)
{
    (void)in_sizes; (void)n_in; (void)out_size;
    const float* feature = (const float*)d_in[0];
    const float* gridz   = (const float*)d_in[1];
    const float* mtx     = (const float*)d_in[2];
    const float* mtxi    = (const float*)d_in[3];
    const float* pr      = (const float*)d_in[4];
    const float* pi      = (const float*)d_in[5];
    float* out = (float*)d_out;

    k_init<<<64, 256>>>(mtx, mtxi, gridz);                   // parallel CSR + twiddles

    k_fft_w_fwd<<<(BD*T_DIM*HW)/16, 256>>>(feature);         // -> fp16 bufA

    k_fft_h_fwd<<<dim3((KW + 15)/16, T_DIM, BD), 256>>>();   // fp16 bufA -> fp16 bufB

    k_fft_t<<<dim3((KW + 7)/8, T_DIM), 256>>>(pr, pi);       // fp16 in, fp32 out (x 1/512)

    k_fft_h_inv<<<dim3((KW + 15)/16, T_DIM, BD), 256>>>();   // fp32 bufC -> fp16 bufA

    k_fft_w_inv<<<(BD*T_DIM*HW)/16, 256>>>(out);             // fp16 bufA -> out (CSR x 2^-16)
}